// round 16
// baseline (speedup 1.0000x reference)
#include <cuda_runtime.h>
#include <cuda_fp16.h>
#include <cstdint>

#define GRIDS 64
#define GP    65            // GRIDS + 1
#define ODIM  128
#define PDIM  64            // INPUT_DIM / 2
#define BATCH 16384
#define CELLS (GP * GP)     // 4225
#define BT    32            // batch tile per block

// fp16 transposed table: fp_t[p][cell][o], cell = ia*65 + ib
__device__ __half g_fpt[(size_t)PDIM * CELLS * ODIM];   // ~69 MB

// ---------------------------------------------------------------------------
// Kernel 1: transpose + fp32->fp16 convert, batched-MLP version.
// Read: 8 independent LDG.128 per thread (batched), then smem stores.
// Write: 4 uint4 per thread (ALL 1024 uint4 per cell), STG.128.
// Output table byte-identical to R6/R14 layout: g_fpt[p][cell][o].
// ---------------------------------------------------------------------------
__global__ __launch_bounds__(256) void kan_transpose(const float* __restrict__ fp) {
    __shared__ float tile[ODIM * (PDIM + 1)];   // [o][p], pad 65
    const int cell = blockIdx.x;
    const float4* src = reinterpret_cast<const float4*>(fp + (size_t)cell * (ODIM * PDIM));

    // Phase 1a: batch all global loads (8 in flight per thread).
    float4 v[8];
#pragma unroll
    for (int k = 0; k < 8; ++k)
        v[k] = __ldcs(&src[threadIdx.x + 256 * k]);   // streaming, coalesced

    // Phase 1b: scatter to smem tile [o][p].
#pragma unroll
    for (int k = 0; k < 8; ++k) {
        int idx = threadIdx.x + 256 * k;
        int o  = idx >> 4;           // 16 float4 per o-row
        int p4 = (idx & 15) << 2;
        float* row = &tile[o * (PDIM + 1) + p4];
        row[0] = v[k].x; row[1] = v[k].y; row[2] = v[k].z; row[3] = v[k].w;
    }
    __syncthreads();

    // Phase 2: each thread builds 4 uint4 (8 halves along o each); 1024 total.
    uint4* dst = reinterpret_cast<uint4*>(g_fpt);
#pragma unroll
    for (int k = 0; k < 4; ++k) {
        int g  = threadIdx.x + 256 * k;    // uint4 index, 0..1023
        int p  = g >> 4;                   // 16 uint4 per (p,cell) row
        int o8 = (g & 15) << 3;
        float f[8];
#pragma unroll
        for (int j = 0; j < 8; ++j)
            f[j] = tile[(o8 + j) * (PDIM + 1) + p];
        uint4 w;
        unsigned* u = &w.x;
#pragma unroll
        for (int j = 0; j < 4; ++j) {
            __half2 h = __floats2half2_rn(f[2 * j], f[2 * j + 1]);
            u[j] = *reinterpret_cast<unsigned*>(&h);
        }
        dst[((size_t)p * CELLS + cell) * (ODIM / 8) + (g & 15)] = w;
    }
}

// ---------------------------------------------------------------------------
// Kernel 2: main gather + bilinear reduction (exact R14 body, untouched).
// Block: 512 threads = 16 o-groups (8 outputs each) x 32 batch columns.
// ---------------------------------------------------------------------------
__global__ __launch_bounds__(512, 2) void kan_main(const float* __restrict__ x,
                                                   const float* __restrict__ borders,
                                                   const float* __restrict__ invlen,
                                                   float* __restrict__ out) {
    __shared__ float sb[GP];
    __shared__ float sl[GRIDS];
    __shared__ int   s_cell[PDIM][BT];
    __shared__ uint2 s_wq[PDIM][BT];     // 4 packed half weights
    __shared__ float so[ODIM][BT + 1];   // epilogue transpose buffer

    const int t  = threadIdx.x;
    const int og = t & 15;     // o-group: owns outputs og*8 .. og*8+7
    const int bi = t >> 4;     // batch index within tile, 0..31
    const int b0 = blockIdx.x * BT;

    if (t < GP)                 sb[t] = borders[t];
    else if (t < GP + GRIDS)    sl[t - GP] = invlen[t - GP];
    __syncthreads();

    // Prologue: indices + packed interpolation weights for all (p, b).
    for (int i = t; i < PDIM * BT; i += 512) {
        int p = i >> 5;        // /32
        int b = i & 31;
        float v1 = x[(size_t)(2 * p) * BATCH + b0 + b];
        float v2 = x[(size_t)(2 * p + 1) * BATCH + b0 + b];

        float e1 = expf(-fabsf(v1));
        float c1 = (v1 > 0.f) ? (1.f - 0.5f * e1) : (0.5f * e1);
        int i1 = (int)(c1 * (float)GRIDS);
        i1 = i1 < 0 ? 0 : (i1 > GRIDS - 1 ? GRIDS - 1 : i1);

        float e2 = expf(-fabsf(v2));
        float c2 = (v2 > 0.f) ? (1.f - 0.5f * e2) : (0.5f * e2);
        int i2 = (int)(c2 * (float)GRIDS);
        i2 = i2 < 0 ? 0 : (i2 > GRIDS - 1 ? GRIDS - 1 : i2);

        float d1 = (v1 - sb[i1]) * sl[i1];
        float d2 = (v2 - sb[i2]) * sl[i2];
        float w11 = d1 * d2;
        float w10 = d1 - w11;
        float w01 = d2 - w11;
        float w00 = 1.f - d1 - w01;

        s_cell[p][b] = i1 * GP + i2;
        __half2 hA = __floats2half2_rn(w00, w01);   // lanes: (w00, w01)
        __half2 hB = __floats2half2_rn(w10, w11);   // lanes: (w10, w11)
        uint2 wq;
        wq.x = *reinterpret_cast<unsigned*>(&hA);
        wq.y = *reinterpret_cast<unsigned*>(&hB);
        s_wq[p][b] = wq;
    }
    __syncthreads();

    float acc[8] = {0.f, 0.f, 0.f, 0.f, 0.f, 0.f, 0.f, 0.f};
    const __half* __restrict__ tab = g_fpt;
    const int oofs = og * 8;

    for (int pg = 0; pg < PDIM / 4; ++pg) {
        __half2 hacc[4];
#pragma unroll
        for (int q = 0; q < 4; ++q) {
            const int p = pg * 4 + q;
            const int   c  = s_cell[p][bi];
            const uint2 wq = s_wq[p][bi];
            const __half2 hA = *reinterpret_cast<const __half2*>(&wq.x);
            const __half2 hB = *reinterpret_cast<const __half2*>(&wq.y);
            const __half2 h00 = __half2half2(__low2half(hA));
            const __half2 h01 = __half2half2(__high2half(hA));
            const __half2 h10 = __half2half2(__low2half(hB));
            const __half2 h11 = __half2half2(__high2half(hB));

            const __half* base = tab + ((size_t)p * CELLS + c) * ODIM + oofs;
            uint4 a0 = *reinterpret_cast<const uint4*>(base);                   // (i1,   i2  )
            uint4 a1 = *reinterpret_cast<const uint4*>(base + ODIM);            // (i1,   i2+1)
            uint4 a2 = *reinterpret_cast<const uint4*>(base + GP * ODIM);       // (i1+1, i2  )
            uint4 a3 = *reinterpret_cast<const uint4*>(base + (GP + 1) * ODIM); // (i1+1, i2+1)

            const unsigned* u0 = &a0.x;
            const unsigned* u1 = &a1.x;
            const unsigned* u2 = &a2.x;
            const unsigned* u3 = &a3.x;
#pragma unroll
            for (int j = 0; j < 4; ++j) {
                __half2 v0 = *reinterpret_cast<const __half2*>(&u0[j]);
                __half2 v1 = *reinterpret_cast<const __half2*>(&u1[j]);
                __half2 v2 = *reinterpret_cast<const __half2*>(&u2[j]);
                __half2 v3 = *reinterpret_cast<const __half2*>(&u3[j]);
                __half2 s = __hmul2(h00, v0);
                s = __hfma2(h01, v1, s);
                s = __hfma2(h10, v2, s);
                s = __hfma2(h11, v3, s);
                if (q == 0) hacc[j] = s;
                else        hacc[j] = __hadd2(hacc[j], s);
            }
        }
#pragma unroll
        for (int j = 0; j < 4; ++j) {
            float2 f = __half22float2(hacc[j]);
            acc[2 * j]     += f.x;
            acc[2 * j + 1] += f.y;
        }
    }

    // Epilogue: transpose through smem for coalesced 128B row stores.
    __syncthreads();
#pragma unroll
    for (int k = 0; k < 8; ++k) so[oofs + k][bi] = acc[k];
    __syncthreads();
    for (int idx = t; idx < ODIM * BT; idx += 512) {
        int o = idx >> 5;   // /32
        int j = idx & 31;
        out[(size_t)o * BATCH + b0 + j] = so[o][j];
    }
}

extern "C" void kernel_launch(void* const* d_in, const int* in_sizes, int n_in,
                              void* d_out, int out_size) {
    const float* x       = (const float*)d_in[0];
    const float* fp      = (const float*)d_in[1];
    const float* borders = (const float*)d_in[2];
    const float* invlen  = (const float*)d_in[3];
    float* out = (float*)d_out;

    kan_transpose<<<CELLS, 256>>>(fp);
    kan_main<<<BATCH / BT, 512>>>(x, borders, invlen, out);
}

// round 17
// speedup vs baseline: 1.0392x; 1.0392x over previous
#include <cuda_runtime.h>
#include <cuda_fp16.h>
#include <cstdint>

#define GRIDS 64
#define GP    65            // GRIDS + 1
#define ODIM  128
#define PDIM  64            // INPUT_DIM / 2
#define BATCH 16384
#define CELLS (GP * GP)     // 4225
#define BT    32            // batch tile per block
#define TTH   512           // transpose threads per block

// fp16 transposed table: fp_t[p][cell][o], cell = ia*65 + ib
__device__ __half g_fpt[(size_t)PDIM * CELLS * ODIM];   // ~69 MB

// ---------------------------------------------------------------------------
// Kernel 1: transpose + fp32->fp16 convert (R6/R14 algorithm, 512 threads).
// 2 cells per block; 4 CTAs/SM x 512 thr = 2048 threads/SM (vs 1536 at 256).
// ---------------------------------------------------------------------------
__global__ __launch_bounds__(TTH) void kan_transpose(const float* __restrict__ fp) {
    __shared__ float tile[ODIM * (PDIM + 1)];   // [o][p], pad 65
    const int cell = blockIdx.x;
    const float4* src = reinterpret_cast<const float4*>(fp + (size_t)cell * (ODIM * PDIM));

    for (int idx = threadIdx.x; idx < (ODIM * PDIM) / 4; idx += TTH) {
        int o  = idx >> 4;           // 16 float4 per o-row
        int p4 = (idx & 15) << 2;
        float4 v = __ldcs(&src[idx]);   // streaming: don't pollute L2
        float* row = &tile[o * (PDIM + 1) + p4];
        row[0] = v.x; row[1] = v.y; row[2] = v.z; row[3] = v.w;
    }
    __syncthreads();

    __half2* dst2 = reinterpret_cast<__half2*>(g_fpt);
    for (int idx = threadIdx.x; idx < (ODIM * PDIM) / 2; idx += TTH) {
        int p  = idx >> 6;           // 64 half2 per (p,cell) row
        int o2 = idx & 63;
        float lo = tile[(2 * o2) * (PDIM + 1) + p];
        float hi = tile[(2 * o2 + 1) * (PDIM + 1) + p];
        dst2[((size_t)p * CELLS + cell) * (ODIM / 2) + o2] =
            __floats2half2_rn(lo, hi);
    }
}

// ---------------------------------------------------------------------------
// Kernel 2: main gather + bilinear reduction (exact R14 body, untouched).
// Block: 512 threads = 16 o-groups (8 outputs each) x 32 batch columns.
// ---------------------------------------------------------------------------
__global__ __launch_bounds__(512, 2) void kan_main(const float* __restrict__ x,
                                                   const float* __restrict__ borders,
                                                   const float* __restrict__ invlen,
                                                   float* __restrict__ out) {
    __shared__ float sb[GP];
    __shared__ float sl[GRIDS];
    __shared__ int   s_cell[PDIM][BT];
    __shared__ uint2 s_wq[PDIM][BT];     // 4 packed half weights
    __shared__ float so[ODIM][BT + 1];   // epilogue transpose buffer

    const int t  = threadIdx.x;
    const int og = t & 15;     // o-group: owns outputs og*8 .. og*8+7
    const int bi = t >> 4;     // batch index within tile, 0..31
    const int b0 = blockIdx.x * BT;

    if (t < GP)                 sb[t] = borders[t];
    else if (t < GP + GRIDS)    sl[t - GP] = invlen[t - GP];
    __syncthreads();

    // Prologue: indices + packed interpolation weights for all (p, b).
    for (int i = t; i < PDIM * BT; i += 512) {
        int p = i >> 5;        // /32
        int b = i & 31;
        float v1 = x[(size_t)(2 * p) * BATCH + b0 + b];
        float v2 = x[(size_t)(2 * p + 1) * BATCH + b0 + b];

        float e1 = expf(-fabsf(v1));
        float c1 = (v1 > 0.f) ? (1.f - 0.5f * e1) : (0.5f * e1);
        int i1 = (int)(c1 * (float)GRIDS);
        i1 = i1 < 0 ? 0 : (i1 > GRIDS - 1 ? GRIDS - 1 : i1);

        float e2 = expf(-fabsf(v2));
        float c2 = (v2 > 0.f) ? (1.f - 0.5f * e2) : (0.5f * e2);
        int i2 = (int)(c2 * (float)GRIDS);
        i2 = i2 < 0 ? 0 : (i2 > GRIDS - 1 ? GRIDS - 1 : i2);

        float d1 = (v1 - sb[i1]) * sl[i1];
        float d2 = (v2 - sb[i2]) * sl[i2];
        float w11 = d1 * d2;
        float w10 = d1 - w11;
        float w01 = d2 - w11;
        float w00 = 1.f - d1 - w01;

        s_cell[p][b] = i1 * GP + i2;
        __half2 hA = __floats2half2_rn(w00, w01);   // lanes: (w00, w01)
        __half2 hB = __floats2half2_rn(w10, w11);   // lanes: (w10, w11)
        uint2 wq;
        wq.x = *reinterpret_cast<unsigned*>(&hA);
        wq.y = *reinterpret_cast<unsigned*>(&hB);
        s_wq[p][b] = wq;
    }
    __syncthreads();

    float acc[8] = {0.f, 0.f, 0.f, 0.f, 0.f, 0.f, 0.f, 0.f};
    const __half* __restrict__ tab = g_fpt;
    const int oofs = og * 8;

    for (int pg = 0; pg < PDIM / 4; ++pg) {
        __half2 hacc[4];
#pragma unroll
        for (int q = 0; q < 4; ++q) {
            const int p = pg * 4 + q;
            const int   c  = s_cell[p][bi];
            const uint2 wq = s_wq[p][bi];
            const __half2 hA = *reinterpret_cast<const __half2*>(&wq.x);
            const __half2 hB = *reinterpret_cast<const __half2*>(&wq.y);
            const __half2 h00 = __half2half2(__low2half(hA));
            const __half2 h01 = __half2half2(__high2half(hA));
            const __half2 h10 = __half2half2(__low2half(hB));
            const __half2 h11 = __half2half2(__high2half(hB));

            const __half* base = tab + ((size_t)p * CELLS + c) * ODIM + oofs;
            uint4 a0 = *reinterpret_cast<const uint4*>(base);                   // (i1,   i2  )
            uint4 a1 = *reinterpret_cast<const uint4*>(base + ODIM);            // (i1,   i2+1)
            uint4 a2 = *reinterpret_cast<const uint4*>(base + GP * ODIM);       // (i1+1, i2  )
            uint4 a3 = *reinterpret_cast<const uint4*>(base + (GP + 1) * ODIM); // (i1+1, i2+1)

            const unsigned* u0 = &a0.x;
            const unsigned* u1 = &a1.x;
            const unsigned* u2 = &a2.x;
            const unsigned* u3 = &a3.x;
#pragma unroll
            for (int j = 0; j < 4; ++j) {
                __half2 v0 = *reinterpret_cast<const __half2*>(&u0[j]);
                __half2 v1 = *reinterpret_cast<const __half2*>(&u1[j]);
                __half2 v2 = *reinterpret_cast<const __half2*>(&u2[j]);
                __half2 v3 = *reinterpret_cast<const __half2*>(&u3[j]);
                __half2 s = __hmul2(h00, v0);
                s = __hfma2(h01, v1, s);
                s = __hfma2(h10, v2, s);
                s = __hfma2(h11, v3, s);
                if (q == 0) hacc[j] = s;
                else        hacc[j] = __hadd2(hacc[j], s);
            }
        }
#pragma unroll
        for (int j = 0; j < 4; ++j) {
            float2 f = __half22float2(hacc[j]);
            acc[2 * j]     += f.x;
            acc[2 * j + 1] += f.y;
        }
    }

    // Epilogue: transpose through smem for coalesced 128B row stores.
    __syncthreads();
#pragma unroll
    for (int k = 0; k < 8; ++k) so[oofs + k][bi] = acc[k];
    __syncthreads();
    for (int idx = t; idx < ODIM * BT; idx += 512) {
        int o = idx >> 5;   // /32
        int j = idx & 31;
        out[(size_t)o * BATCH + b0 + j] = so[o][j];
    }
}

extern "C" void kernel_launch(void* const* d_in, const int* in_sizes, int n_in,
                              void* d_out, int out_size) {
    const float* x       = (const float*)d_in[0];
    const float* fp      = (const float*)d_in[1];
    const float* borders = (const float*)d_in[2];
    const float* invlen  = (const float*)d_in[3];
    float* out = (float*)d_out;

    kan_transpose<<<CELLS, TTH>>>(fp);
    kan_main<<<BATCH / BT, 512>>>(x, borders, invlen, out);
}